// round 8
// baseline (speedup 1.0000x reference)
#include <cuda_runtime.h>
#include <cstdint>

#define BATCH 8
#define SEQ   4096
#define DIM   256
#define SPLITK 8
#define SCHUNK (SEQ/SPLITK)   // 512
#define KC 16                 // k-chunk, double buffered

// Scratch (no allocs allowed -> __device__ globals)
__device__ float g_KVp[SPLITK*BATCH*DIM*DIM];  // split-K partials [sp][b][d][e]
__device__ float g_KV [BATCH*DIM*DIM];         // KV (tf32-rounded) [b][d][e]
__device__ float g_ksp[BATCH*SPLITK*DIM];      // k_sum split partials
__device__ float g_ks [BATCH*DIM];             // k_sum[b][d]

__device__ __forceinline__ float phi(float x){
    // sigmoid(0.6053*x - 4.102) = 1/(1+exp(4.102 - 0.6053*x))
    return 1.0f / (1.0f + __expf(4.102f - 0.6053f * x));
}
__device__ __forceinline__ uint32_t to_tf32(float x){
    uint32_t r; asm("cvt.rna.tf32.f32 %0, %1;" : "=r"(r) : "f"(x)); return r;
}
__device__ __forceinline__ uint32_t f2tf(uint32_t raw){
    return to_tf32(__uint_as_float(raw));
}
__device__ __forceinline__ void mma8(float c[4], const uint32_t a[4],
                                     uint32_t b0, uint32_t b1){
    asm volatile("mma.sync.aligned.m16n8k8.row.col.f32.tf32.tf32.f32 "
        "{%0,%1,%2,%3},{%4,%5,%6,%7},{%8,%9},{%0,%1,%2,%3};"
        : "+f"(c[0]),"+f"(c[1]),"+f"(c[2]),"+f"(c[3])
        : "r"(a[0]),"r"(a[1]),"r"(a[2]),"r"(a[3]),"r"(b0),"r"(b1));
}
__device__ __forceinline__ uint32_t smem_u32(const void* p){
    uint32_t a;
    asm("{ .reg .u64 t; cvta.to.shared.u64 t, %1; cvt.u32.u64 %0, t; }" : "=r"(a) : "l"(p));
    return a;
}
__device__ __forceinline__ void cp16(uint32_t dst, const void* src){
    asm volatile("cp.async.ca.shared.global [%0], [%1], 16;" :: "r"(dst), "l"(src));
}
__device__ __forceinline__ void cp_commit(){ asm volatile("cp.async.commit_group;"); }
__device__ __forceinline__ void cp_wait0(){ asm volatile("cp.async.wait_group 0;"); }

// ---------------------------------------------------------------------------
// GEMM 1 (tf32 mma, split-K): KVp[sp][b][d][e] += phi(K[b][s][d]) * V[b][s][e]
// CTA tile 128(d) x 256(e), 8 warps of 64x64 (2m x 4n), KC=16 double buffered.
// A = phi(K) tf32 in SMEM [k][m] s136; B = V raw via cp.async [k][n] s264.
// Fused k_sum partials. grid (2,8,8) = 128 CTAs = 1 wave @ 1 CTA/SM.
// ---------------------------------------------------------------------------
#define G1_OFF_A  0                      // 2*16*136*4 = 17408
#define G1_OFF_B  17408                  // 2*16*264*4 = 33792
#define G1_OFF_KS 51200                  // 16*128*4   = 8192
#define G1_SMEM   59392

__global__ __launch_bounds__(256,1) void kv_part_kernel(const float* __restrict__ K,
                                                        const float* __restrict__ V){
    extern __shared__ char smraw[];
    uint32_t (*As)[16][136] = (uint32_t(*)[16][136])(smraw + G1_OFF_A);
    uint32_t (*Bs)[16][264] = (uint32_t(*)[16][264])(smraw + G1_OFF_B);
    float* ksred = (float*)(smraw + G1_OFF_KS);   // [16 groups][128 d]

    int b = blockIdx.z, sp = blockIdx.y, dt = blockIdx.x;
    int t = threadIdx.x, lane = t & 31, w = t >> 5;
    int wm = (w & 1)*64, wn = (w >> 1)*64;
    int gid = lane >> 2, tig = lane & 3;

    const float* Kb = K + ((size_t)b*SEQ + (size_t)sp*SCHUNK)*DIM + dt*128;
    const float* Vb = V + ((size_t)b*SEQ + (size_t)sp*SCHUNK)*DIM;

    int lrow = t >> 4, lc = (t & 15)*4;
    float ksum_p[8] = {};
    float4 kreg[2];

    // ---- prologue: chunk 0 ----
    kreg[0] = *(const float4*)(Kb + (size_t)lrow*DIM + lc);
    kreg[1] = *(const float4*)(Kb + (size_t)lrow*DIM + lc + 64);
    #pragma unroll
    for (int j = 0; j < 4; j++)
        cp16(smem_u32(&Bs[0][lrow][lc + 64*j]), Vb + (size_t)lrow*DIM + lc + 64*j);
    cp_commit();
    #pragma unroll
    for (int p = 0; p < 2; p++){
        float f0=phi(kreg[p].x), f1=phi(kreg[p].y), f2=phi(kreg[p].z), f3=phi(kreg[p].w);
        ksum_p[p*4+0]+=f0; ksum_p[p*4+1]+=f1; ksum_p[p*4+2]+=f2; ksum_p[p*4+3]+=f3;
        uint4 u = { to_tf32(f0), to_tf32(f1), to_tf32(f2), to_tf32(f3) };
        *(uint4*)&As[0][lrow][lc + 64*p] = u;
    }
    cp_wait0();
    __syncthreads();

    float acc[4][8][4] = {};
    int stage = 0;
    for (int k0 = 0; k0 < SCHUNK; k0 += KC){
        int nxt = stage ^ 1;
        bool hn = (k0 + KC) < SCHUNK;
        if (hn){
            kreg[0] = *(const float4*)(Kb + (size_t)(k0+KC+lrow)*DIM + lc);
            kreg[1] = *(const float4*)(Kb + (size_t)(k0+KC+lrow)*DIM + lc + 64);
            #pragma unroll
            for (int j = 0; j < 4; j++)
                cp16(smem_u32(&Bs[nxt][lrow][lc + 64*j]),
                     Vb + (size_t)(k0+KC+lrow)*DIM + lc + 64*j);
            cp_commit();
        }
        #pragma unroll
        for (int kk = 0; kk < KC; kk += 8){
            uint32_t bf[8][2];
            #pragma unroll
            for (int ni = 0; ni < 8; ni++){
                int n = wn + ni*8 + gid;
                bf[ni][0] = f2tf(Bs[stage][kk+tig  ][n]);
                bf[ni][1] = f2tf(Bs[stage][kk+tig+4][n]);
            }
            uint32_t af[4][4];
            #pragma unroll
            for (int mi = 0; mi < 4; mi++){
                int m = wm + mi*16 + gid;
                af[mi][0] = As[stage][kk+tig  ][m  ];
                af[mi][1] = As[stage][kk+tig  ][m+8];
                af[mi][2] = As[stage][kk+tig+4][m  ];
                af[mi][3] = As[stage][kk+tig+4][m+8];
            }
            #pragma unroll
            for (int mi = 0; mi < 4; mi++)
                #pragma unroll
                for (int ni = 0; ni < 8; ni++)
                    mma8(acc[mi][ni], af[mi], bf[ni][0], bf[ni][1]);
        }
        if (hn){
            #pragma unroll
            for (int p = 0; p < 2; p++){
                float f0=phi(kreg[p].x), f1=phi(kreg[p].y), f2=phi(kreg[p].z), f3=phi(kreg[p].w);
                ksum_p[p*4+0]+=f0; ksum_p[p*4+1]+=f1; ksum_p[p*4+2]+=f2; ksum_p[p*4+3]+=f3;
                uint4 u = { to_tf32(f0), to_tf32(f1), to_tf32(f2), to_tf32(f3) };
                *(uint4*)&As[nxt][lrow][lc + 64*p] = u;
            }
        }
        cp_wait0();
        __syncthreads();
        stage = nxt;
    }

    // fused k_sum partial: thread owns d-cols lc..lc+3 and lc+64.. within group lrow
    *(float4*)&ksred[lrow*128 + lc]      = make_float4(ksum_p[0],ksum_p[1],ksum_p[2],ksum_p[3]);
    *(float4*)&ksred[lrow*128 + lc + 64] = make_float4(ksum_p[4],ksum_p[5],ksum_p[6],ksum_p[7]);
    __syncthreads();
    if (t < 128){
        float s = 0.f;
        #pragma unroll
        for (int g = 0; g < 16; g++) s += ksred[g*128 + t];
        g_ksp[(b*SPLITK + sp)*DIM + dt*128 + t] = s;
    }

    float* outp = g_KVp + (((size_t)sp*BATCH + b)*DIM + dt*128)*DIM;
    #pragma unroll
    for (int mi = 0; mi < 4; mi++)
        #pragma unroll
        for (int ni = 0; ni < 8; ni++){
            int r = wm + mi*16 + gid, c = wn + ni*8 + tig*2;
            float2 v0 = {acc[mi][ni][0], acc[mi][ni][1]};
            float2 v1 = {acc[mi][ni][2], acc[mi][ni][3]};
            *(float2*)(outp + (size_t)r*DIM + c)     = v0;
            *(float2*)(outp + (size_t)(r+8)*DIM + c) = v1;
        }
}

__global__ __launch_bounds__(256) void ksum_reduce_kernel(){
    int i = blockIdx.x*256 + threadIdx.x;
    int b = i / DIM, d = i % DIM;
    float acc = 0.f;
    #pragma unroll
    for (int sp = 0; sp < SPLITK; sp++) acc += g_ksp[(b*SPLITK + sp)*DIM + d];
    g_ks[i] = acc;
}

// kv_reduce: sum split-K partials AND pre-round to tf32 (removes cvt from GEMM2)
__global__ __launch_bounds__(256) void kv_reduce_kernel(){
    int i = (blockIdx.x*256 + threadIdx.x)*4;
    float4 acc = {0.f,0.f,0.f,0.f};
    #pragma unroll
    for (int s = 0; s < SPLITK; s++){
        float4 v = *(const float4*)&g_KVp[(size_t)s*BATCH*DIM*DIM + i];
        acc.x += v.x; acc.y += v.y; acc.z += v.z; acc.w += v.w;
    }
    uint4 r = { to_tf32(acc.x), to_tf32(acc.y), to_tf32(acc.z), to_tf32(acc.w) };
    *(uint4*)&g_KV[i] = r;
}

// ---------------------------------------------------------------------------
// GEMM 2 (tf32 mma): Out[b][s][e] = (phi(Q).KV)/(phi(Q).k_sum)
// CTA tile 128(s) x 256(e) -- full N, no redundant phi(Q). 8 warps 64x64.
// A = phi(Q) tf32 [m][k] s20; B = g_KV (pre-rounded tf32) via cp.async [k][n] s264.
// Fused bottom. grid (32, 8) = 256 CTAs.
// ---------------------------------------------------------------------------
#define G2_OFF_A    0                    // 2*128*20*4 = 20480
#define G2_OFF_B    20480                // 2*16*264*4 = 33792
#define G2_OFF_INVB 54272                // 512
#define G2_OFF_KS   54784                // 1024
#define G2_SMEM     55808

__global__ __launch_bounds__(256,1) void out_kernel(const float* __restrict__ Q,
                                                    float* __restrict__ Out){
    extern __shared__ char smraw[];
    uint32_t (*As)[128][20] = (uint32_t(*)[128][20])(smraw + G2_OFF_A);
    uint32_t (*Bs)[16][264] = (uint32_t(*)[16][264])(smraw + G2_OFF_B);
    float* invb = (float*)(smraw + G2_OFF_INVB);
    float* ks_s = (float*)(smraw + G2_OFF_KS);

    int st = blockIdx.x, b = blockIdx.y;
    int t = threadIdx.x, lane = t & 31, w = t >> 5;
    int wm = (w & 1)*64, wn = (w >> 1)*64;
    int gid = lane >> 2, tig = lane & 3;

    const float* Qb  = Q + ((size_t)b*SEQ + st*128)*DIM;
    const float* KVb = g_KV + (size_t)b*DIM*DIM;

    ks_s[t] = g_ks[b*DIM + t];

    int a_s = t >> 2, a_c = (t & 3)*4;      // A loader: rows a_s, a_s+64
    int b_r = t >> 4, b_c = (t & 15)*4;     // B loader: row b_r, 4 x 64-col segments
    float bot_p[2] = {0.f, 0.f};
    float4 qreg[2];

    // ---- prologue: chunk 0 ----
    qreg[0] = *(const float4*)(Qb + (size_t)a_s*DIM + a_c);
    qreg[1] = *(const float4*)(Qb + (size_t)(a_s+64)*DIM + a_c);
    #pragma unroll
    for (int j = 0; j < 4; j++)
        cp16(smem_u32(&Bs[0][b_r][b_c + 64*j]), KVb + (size_t)b_r*DIM + b_c + 64*j);
    cp_commit();
    __syncthreads();            // ks_s visible
    #pragma unroll
    for (int p = 0; p < 2; p++){
        float f0=phi(qreg[p].x), f1=phi(qreg[p].y), f2=phi(qreg[p].z), f3=phi(qreg[p].w);
        bot_p[p] += f0*ks_s[a_c] + f1*ks_s[a_c+1] + f2*ks_s[a_c+2] + f3*ks_s[a_c+3];
        uint4 u = { to_tf32(f0), to_tf32(f1), to_tf32(f2), to_tf32(f3) };
        *(uint4*)&As[0][a_s + p*64][a_c] = u;
    }
    cp_wait0();
    __syncthreads();

    float acc[4][8][4] = {};
    int stage = 0;
    for (int k0 = 0; k0 < DIM; k0 += KC){
        int nxt = stage ^ 1;
        bool hn = (k0 + KC) < DIM;
        if (hn){
            qreg[0] = *(const float4*)(Qb + (size_t)a_s*DIM + k0 + KC + a_c);
            qreg[1] = *(const float4*)(Qb + (size_t)(a_s+64)*DIM + k0 + KC + a_c);
            #pragma unroll
            for (int j = 0; j < 4; j++)
                cp16(smem_u32(&Bs[nxt][b_r][b_c + 64*j]),
                     KVb + (size_t)(k0 + KC + b_r)*DIM + b_c + 64*j);
            cp_commit();
        }
        #pragma unroll
        for (int kk = 0; kk < KC; kk += 8){
            uint32_t bf[8][2];
            #pragma unroll
            for (int ni = 0; ni < 8; ni++){
                int n = wn + ni*8 + gid;
                bf[ni][0] = Bs[stage][kk+tig  ][n];   // pre-rounded tf32
                bf[ni][1] = Bs[stage][kk+tig+4][n];
            }
            uint32_t af[4][4];
            #pragma unroll
            for (int mi = 0; mi < 4; mi++){
                int m = wm + mi*16 + gid;
                af[mi][0] = As[stage][m  ][kk+tig  ];
                af[mi][1] = As[stage][m+8][kk+tig  ];
                af[mi][2] = As[stage][m  ][kk+tig+4];
                af[mi][3] = As[stage][m+8][kk+tig+4];
            }
            #pragma unroll
            for (int mi = 0; mi < 4; mi++)
                #pragma unroll
                for (int ni = 0; ni < 8; ni++)
                    mma8(acc[mi][ni], af[mi], bf[ni][0], bf[ni][1]);
        }
        if (hn){
            #pragma unroll
            for (int p = 0; p < 2; p++){
                float f0=phi(qreg[p].x), f1=phi(qreg[p].y), f2=phi(qreg[p].z), f3=phi(qreg[p].w);
                int k = k0 + KC + a_c;
                bot_p[p] += f0*ks_s[k] + f1*ks_s[k+1] + f2*ks_s[k+2] + f3*ks_s[k+3];
                uint4 u = { to_tf32(f0), to_tf32(f1), to_tf32(f2), to_tf32(f3) };
                *(uint4*)&As[nxt][a_s + p*64][a_c] = u;
            }
        }
        cp_wait0();
        __syncthreads();
        stage = nxt;
    }

    // fused bottom: reduce over the 4 lanes (t&3) sharing each row
    #pragma unroll
    for (int p = 0; p < 2; p++){
        bot_p[p] += __shfl_xor_sync(0xffffffffu, bot_p[p], 1);
        bot_p[p] += __shfl_xor_sync(0xffffffffu, bot_p[p], 2);
    }
    if ((t & 3) == 0){
        invb[a_s]      = 1.0f / bot_p[0];
        invb[a_s + 64] = 1.0f / bot_p[1];
    }
    __syncthreads();

    float* outp = Out + ((size_t)b*SEQ + st*128)*DIM;
    #pragma unroll
    for (int mi = 0; mi < 4; mi++)
        #pragma unroll
        for (int ni = 0; ni < 8; ni++){
            int r = wm + mi*16 + gid, c = wn + ni*8 + tig*2;
            float ib0 = invb[r], ib1 = invb[r+8];
            float2 v0 = {acc[mi][ni][0]*ib0, acc[mi][ni][1]*ib0};
            float2 v1 = {acc[mi][ni][2]*ib1, acc[mi][ni][3]*ib1};
            *(float2*)(outp + (size_t)r*DIM + c)     = v0;
            *(float2*)(outp + (size_t)(r+8)*DIM + c) = v1;
        }
}

// ---------------------------------------------------------------------------
extern "C" void kernel_launch(void* const* d_in, const int* in_sizes, int n_in,
                              void* d_out, int out_size){
    const float* Q = (const float*)d_in[0];
    const float* K = (const float*)d_in[1];
    const float* V = (const float*)d_in[2];
    float* Out = (float*)d_out;

    cudaFuncSetAttribute(kv_part_kernel,
                         cudaFuncAttributeMaxDynamicSharedMemorySize, G1_SMEM);
    cudaFuncSetAttribute(out_kernel,
                         cudaFuncAttributeMaxDynamicSharedMemorySize, G2_SMEM);

    kv_part_kernel    <<<dim3(2, SPLITK, BATCH), 256, G1_SMEM>>>(K, V);
    ksum_reduce_kernel<<<(BATCH*DIM)/256, 256>>>();
    kv_reduce_kernel  <<<(BATCH*DIM*DIM)/(256*4), 256>>>();
    out_kernel        <<<dim3(32, BATCH), 256, G2_SMEM>>>(Q, Out);
}

// round 9
// speedup vs baseline: 1.0089x; 1.0089x over previous
#include <cuda_runtime.h>
#include <cstdint>

#define BATCH 8
#define SEQ   4096
#define DIM   256
#define SPLITK 8
#define SCHUNK (SEQ/SPLITK)   // 512
#define KC 32                 // k-chunk, double buffered

// Scratch (no allocs allowed -> __device__ globals)
__device__ float g_KVp[SPLITK*BATCH*DIM*DIM];  // split-K partials [sp][b][d][e]
__device__ float g_KV [BATCH*DIM*DIM];         // KV (tf32-rounded) [b][d][e]
__device__ float g_ksp[BATCH*SPLITK*DIM];      // k_sum split partials
__device__ float g_ks [BATCH*DIM];             // k_sum[b][d]

__device__ __forceinline__ float phi(float x){
    // sigmoid(0.6053*x - 4.102) = 1/(1+exp(4.102 - 0.6053*x))
    return 1.0f / (1.0f + __expf(4.102f - 0.6053f * x));
}
__device__ __forceinline__ uint32_t to_tf32(float x){
    uint32_t r; asm("cvt.rna.tf32.f32 %0, %1;" : "=r"(r) : "f"(x)); return r;
}
__device__ __forceinline__ uint32_t f2tf(uint32_t raw){
    return to_tf32(__uint_as_float(raw));
}
__device__ __forceinline__ void mma8(float c[4], const uint32_t a[4],
                                     uint32_t b0, uint32_t b1){
    asm volatile("mma.sync.aligned.m16n8k8.row.col.f32.tf32.tf32.f32 "
        "{%0,%1,%2,%3},{%4,%5,%6,%7},{%8,%9},{%0,%1,%2,%3};"
        : "+f"(c[0]),"+f"(c[1]),"+f"(c[2]),"+f"(c[3])
        : "r"(a[0]),"r"(a[1]),"r"(a[2]),"r"(a[3]),"r"(b0),"r"(b1));
}
__device__ __forceinline__ uint32_t smem_u32(const void* p){
    uint32_t a;
    asm("{ .reg .u64 t; cvta.to.shared.u64 t, %1; cvt.u32.u64 %0, t; }" : "=r"(a) : "l"(p));
    return a;
}
__device__ __forceinline__ void cp16(uint32_t dst, const void* src){
    asm volatile("cp.async.ca.shared.global [%0], [%1], 16;" :: "r"(dst), "l"(src));
}
__device__ __forceinline__ void cp_commit(){ asm volatile("cp.async.commit_group;"); }
__device__ __forceinline__ void cp_wait0(){ asm volatile("cp.async.wait_group 0;"); }

// ---------------------------------------------------------------------------
// GEMM 1 (tf32 mma, split-K): KVp[sp][b][d][e] += phi(K[b][s][d]) * V[b][s][e]
// CTA tile 128(d)x128(e), 8 warps of 64x32 (2m x 4n), KC=32 double buffered.
// A = phi(K) tf32 [k][m] s136; B = V raw via cp.async [k][n] s136 (f2tf at read).
// Fused k_sum partials. grid (4,8,8) = 256 CTAs = one 2-CTA/SM wave.
// ---------------------------------------------------------------------------
#define G1_OFF_A  0                      // 2*32*136*4 = 34816
#define G1_OFF_B  34816                  // 2*32*136*4 = 34816
#define G1_OFF_KS 69632                  // 8*128*4    = 4096
#define G1_SMEM   73728

__global__ __launch_bounds__(256,2) void kv_part_kernel(const float* __restrict__ K,
                                                        const float* __restrict__ V){
    extern __shared__ char smraw[];
    uint32_t (*As)[KC][136] = (uint32_t(*)[KC][136])(smraw + G1_OFF_A);
    uint32_t (*Bs)[KC][136] = (uint32_t(*)[KC][136])(smraw + G1_OFF_B);
    float* ksred = (float*)(smraw + G1_OFF_KS);   // [8 warps][128 d]

    int b = blockIdx.z, sp = blockIdx.y;
    int dt = blockIdx.x >> 1, et = blockIdx.x & 1;
    int t = threadIdx.x, lane = t & 31, w = t >> 5;
    int wm = (w & 1)*64, wn = (w >> 1)*32;
    int gid = lane >> 2, tig = lane & 3;

    const float* Kb = K + ((size_t)b*SEQ + (size_t)sp*SCHUNK)*DIM + dt*128;
    const float* Vb = V + ((size_t)b*SEQ + (size_t)sp*SCHUNK)*DIM + et*128;

    int col4 = lane*4;                  // loader: d/e cols col4..+3, rows w+8p
    float ksum_p[4] = {};
    float4 kreg[4];

    // ---- prologue: chunk 0 ----
    #pragma unroll
    for (int p = 0; p < 4; p++){
        kreg[p] = *(const float4*)(Kb + (size_t)(w+8*p)*DIM + col4);
        cp16(smem_u32(&Bs[0][w+8*p][col4]), Vb + (size_t)(w+8*p)*DIM + col4);
    }
    cp_commit();
    #pragma unroll
    for (int p = 0; p < 4; p++){
        float f0=phi(kreg[p].x), f1=phi(kreg[p].y), f2=phi(kreg[p].z), f3=phi(kreg[p].w);
        ksum_p[0]+=f0; ksum_p[1]+=f1; ksum_p[2]+=f2; ksum_p[3]+=f3;
        uint4 u = { to_tf32(f0), to_tf32(f1), to_tf32(f2), to_tf32(f3) };
        *(uint4*)&As[0][w+8*p][col4] = u;
    }
    cp_wait0();
    __syncthreads();

    float acc[4][4][4] = {};
    int stage = 0;
    for (int k0 = 0; k0 < SCHUNK; k0 += KC){
        int nxt = stage ^ 1;
        bool hn = (k0 + KC) < SCHUNK;
        if (hn){
            #pragma unroll
            for (int p = 0; p < 4; p++){
                kreg[p] = *(const float4*)(Kb + (size_t)(k0+KC+w+8*p)*DIM + col4);
                cp16(smem_u32(&Bs[nxt][w+8*p][col4]),
                     Vb + (size_t)(k0+KC+w+8*p)*DIM + col4);
            }
            cp_commit();
        }
        #pragma unroll
        for (int kk = 0; kk < KC; kk += 8){
            uint32_t bf[4][2];
            #pragma unroll
            for (int ni = 0; ni < 4; ni++){
                int n = wn + ni*8 + gid;
                bf[ni][0] = f2tf(Bs[stage][kk+tig  ][n]);
                bf[ni][1] = f2tf(Bs[stage][kk+tig+4][n]);
            }
            uint32_t af[4][4];
            #pragma unroll
            for (int mi = 0; mi < 4; mi++){
                int m = wm + mi*16 + gid;
                af[mi][0] = As[stage][kk+tig  ][m  ];
                af[mi][1] = As[stage][kk+tig  ][m+8];
                af[mi][2] = As[stage][kk+tig+4][m  ];
                af[mi][3] = As[stage][kk+tig+4][m+8];
            }
            #pragma unroll
            for (int mi = 0; mi < 4; mi++)
                #pragma unroll
                for (int ni = 0; ni < 4; ni++)
                    mma8(acc[mi][ni], af[mi], bf[ni][0], bf[ni][1]);
        }
        if (hn){
            #pragma unroll
            for (int p = 0; p < 4; p++){
                float f0=phi(kreg[p].x), f1=phi(kreg[p].y), f2=phi(kreg[p].z), f3=phi(kreg[p].w);
                ksum_p[0]+=f0; ksum_p[1]+=f1; ksum_p[2]+=f2; ksum_p[3]+=f3;
                uint4 u = { to_tf32(f0), to_tf32(f1), to_tf32(f2), to_tf32(f3) };
                *(uint4*)&As[nxt][w+8*p][col4] = u;
            }
        }
        cp_wait0();
        __syncthreads();
        stage = nxt;
    }

    // fused k_sum partial: each warp covers all 128 d-cols; reduce across 8 warps
    *(float4*)&ksred[w*128 + col4] = make_float4(ksum_p[0],ksum_p[1],ksum_p[2],ksum_p[3]);
    __syncthreads();
    if (et == 0 && t < 128){
        float s = 0.f;
        #pragma unroll
        for (int g = 0; g < 8; g++) s += ksred[g*128 + t];
        g_ksp[(b*SPLITK + sp)*DIM + dt*128 + t] = s;
    }

    float* outp = g_KVp + (((size_t)sp*BATCH + b)*DIM + dt*128)*DIM + et*128;
    #pragma unroll
    for (int mi = 0; mi < 4; mi++)
        #pragma unroll
        for (int ni = 0; ni < 4; ni++){
            int r = wm + mi*16 + gid, c = wn + ni*8 + tig*2;
            float2 v0 = {acc[mi][ni][0], acc[mi][ni][1]};
            float2 v1 = {acc[mi][ni][2], acc[mi][ni][3]};
            *(float2*)(outp + (size_t)r*DIM + c)     = v0;
            *(float2*)(outp + (size_t)(r+8)*DIM + c) = v1;
        }
}

__global__ __launch_bounds__(256) void ksum_reduce_kernel(){
    int i = blockIdx.x*256 + threadIdx.x;
    int b = i / DIM, d = i % DIM;
    float acc = 0.f;
    #pragma unroll
    for (int sp = 0; sp < SPLITK; sp++) acc += g_ksp[(b*SPLITK + sp)*DIM + d];
    g_ks[i] = acc;
}

// kv_reduce: sum split-K partials AND pre-round to tf32 (removes cvt from GEMM2)
__global__ __launch_bounds__(256) void kv_reduce_kernel(){
    int i = (blockIdx.x*256 + threadIdx.x)*4;
    float4 acc = {0.f,0.f,0.f,0.f};
    #pragma unroll
    for (int s = 0; s < SPLITK; s++){
        float4 v = *(const float4*)&g_KVp[(size_t)s*BATCH*DIM*DIM + i];
        acc.x += v.x; acc.y += v.y; acc.z += v.z; acc.w += v.w;
    }
    uint4 r = { to_tf32(acc.x), to_tf32(acc.y), to_tf32(acc.z), to_tf32(acc.w) };
    *(uint4*)&g_KV[i] = r;
}

// ---------------------------------------------------------------------------
// GEMM 2 (tf32 mma): Out[b][s][e] = (phi(Q).KV)/(phi(Q).k_sum)
// CTA tile 128(s)x128(e), 8 warps 64x32, KC=32 double buffered.
// A = phi(Q) tf32 [m][k] s36; B = g_KV (pre-rounded tf32) via cp.async [k][n] s136.
// Fused bottom. grid (2, 32, 8) = 512 CTAs.
// ---------------------------------------------------------------------------
#define G2_OFF_A    0                    // 2*128*36*4 = 36864
#define G2_OFF_B    36864                // 2*32*136*4 = 34816
#define G2_OFF_INVB 71680                // 512
#define G2_OFF_KS   72192                // 1024
#define G2_SMEM     73216

__global__ __launch_bounds__(256,2) void out_kernel(const float* __restrict__ Q,
                                                    float* __restrict__ Out){
    extern __shared__ char smraw[];
    uint32_t (*As)[128][36] = (uint32_t(*)[128][36])(smraw + G2_OFF_A);
    uint32_t (*Bs)[KC][136] = (uint32_t(*)[KC][136])(smraw + G2_OFF_B);
    float* invb = (float*)(smraw + G2_OFF_INVB);
    float* ks_s = (float*)(smraw + G2_OFF_KS);

    int et = blockIdx.x, st = blockIdx.y, b = blockIdx.z;
    int t = threadIdx.x, lane = t & 31, w = t >> 5;
    int wm = (w & 1)*64, wn = (w >> 1)*32;
    int gid = lane >> 2, tig = lane & 3;

    const float* Qb  = Q + ((size_t)b*SEQ + st*128)*DIM;
    const float* KVb = g_KV + (size_t)b*DIM*DIM + et*128;

    ks_s[t] = g_ks[b*DIM + t];

    int a_row = t >> 1, a_c = (t & 1)*16;  // A loader: row a_row, 16 k-cols
    int col4 = lane*4;                      // B loader: rows w+8p, cols col4
    float bot_p = 0.f;
    float4 qreg[4];

    // ---- prologue: chunk 0 ----
    #pragma unroll
    for (int j = 0; j < 4; j++)
        qreg[j] = *(const float4*)(Qb + (size_t)a_row*DIM + a_c + j*4);
    #pragma unroll
    for (int p = 0; p < 4; p++)
        cp16(smem_u32(&Bs[0][w+8*p][col4]), KVb + (size_t)(w+8*p)*DIM + col4);
    cp_commit();
    __syncthreads();            // ks_s visible
    #pragma unroll
    for (int j = 0; j < 4; j++){
        float f0=phi(qreg[j].x), f1=phi(qreg[j].y), f2=phi(qreg[j].z), f3=phi(qreg[j].w);
        int k = a_c + j*4;
        bot_p += f0*ks_s[k] + f1*ks_s[k+1] + f2*ks_s[k+2] + f3*ks_s[k+3];
        uint4 u = { to_tf32(f0), to_tf32(f1), to_tf32(f2), to_tf32(f3) };
        *(uint4*)&As[0][a_row][a_c + j*4] = u;
    }
    cp_wait0();
    __syncthreads();

    float acc[4][4][4] = {};
    int stage = 0;
    for (int k0 = 0; k0 < DIM; k0 += KC){
        int nxt = stage ^ 1;
        bool hn = (k0 + KC) < DIM;
        if (hn){
            #pragma unroll
            for (int j = 0; j < 4; j++)
                qreg[j] = *(const float4*)(Qb + (size_t)a_row*DIM + k0 + KC + a_c + j*4);
            #pragma unroll
            for (int p = 0; p < 4; p++)
                cp16(smem_u32(&Bs[nxt][w+8*p][col4]),
                     KVb + (size_t)(k0+KC+w+8*p)*DIM + col4);
            cp_commit();
        }
        #pragma unroll
        for (int kk = 0; kk < KC; kk += 8){
            uint32_t bf[4][2];
            #pragma unroll
            for (int ni = 0; ni < 4; ni++){
                int n = wn + ni*8 + gid;
                bf[ni][0] = Bs[stage][kk+tig  ][n];   // pre-rounded tf32
                bf[ni][1] = Bs[stage][kk+tig+4][n];
            }
            uint32_t af[4][4];
            #pragma unroll
            for (int mi = 0; mi < 4; mi++){
                int m = wm + mi*16 + gid;
                af[mi][0] = As[stage][m  ][kk+tig  ];
                af[mi][1] = As[stage][m+8][kk+tig  ];
                af[mi][2] = As[stage][m  ][kk+tig+4];
                af[mi][3] = As[stage][m+8][kk+tig+4];
            }
            #pragma unroll
            for (int mi = 0; mi < 4; mi++)
                #pragma unroll
                for (int ni = 0; ni < 4; ni++)
                    mma8(acc[mi][ni], af[mi], bf[ni][0], bf[ni][1]);
        }
        if (hn){
            #pragma unroll
            for (int j = 0; j < 4; j++){
                float f0=phi(qreg[j].x), f1=phi(qreg[j].y), f2=phi(qreg[j].z), f3=phi(qreg[j].w);
                int k = k0 + KC + a_c + j*4;
                bot_p += f0*ks_s[k] + f1*ks_s[k+1] + f2*ks_s[k+2] + f3*ks_s[k+3];
                uint4 u = { to_tf32(f0), to_tf32(f1), to_tf32(f2), to_tf32(f3) };
                *(uint4*)&As[nxt][a_row][a_c + j*4] = u;
            }
        }
        cp_wait0();
        __syncthreads();
        stage = nxt;
    }

    // fused bottom: two threads (t, t^1) share row a_row
    bot_p += __shfl_xor_sync(0xffffffffu, bot_p, 1);
    if ((t & 1) == 0) invb[a_row] = 1.0f / bot_p;
    __syncthreads();

    float* outp = Out + ((size_t)b*SEQ + st*128)*DIM + et*128;
    #pragma unroll
    for (int mi = 0; mi < 4; mi++)
        #pragma unroll
        for (int ni = 0; ni < 4; ni++){
            int r = wm + mi*16 + gid, c = wn + ni*8 + tig*2;
            float ib0 = invb[r], ib1 = invb[r+8];
            float2 v0 = {acc[mi][ni][0]*ib0, acc[mi][ni][1]*ib0};
            float2 v1 = {acc[mi][ni][2]*ib1, acc[mi][ni][3]*ib1};
            *(float2*)(outp + (size_t)r*DIM + c)     = v0;
            *(float2*)(outp + (size_t)(r+8)*DIM + c) = v1;
        }
}

// ---------------------------------------------------------------------------
extern "C" void kernel_launch(void* const* d_in, const int* in_sizes, int n_in,
                              void* d_out, int out_size){
    const float* Q = (const float*)d_in[0];
    const float* K = (const float*)d_in[1];
    const float* V = (const float*)d_in[2];
    float* Out = (float*)d_out;

    cudaFuncSetAttribute(kv_part_kernel,
                         cudaFuncAttributeMaxDynamicSharedMemorySize, G1_SMEM);
    cudaFuncSetAttribute(out_kernel,
                         cudaFuncAttributeMaxDynamicSharedMemorySize, G2_SMEM);

    kv_part_kernel    <<<dim3(4, SPLITK, BATCH), 256, G1_SMEM>>>(K, V);
    ksum_reduce_kernel<<<(BATCH*DIM)/256, 256>>>();
    kv_reduce_kernel  <<<(BATCH*DIM*DIM)/(256*4), 256>>>();
    out_kernel        <<<dim3(2, 32, BATCH), 256, G2_SMEM>>>(Q, Out);
}